// round 6
// baseline (speedup 1.0000x reference)
#include <cuda_runtime.h>
#include <cuda_fp16.h>
#include <cstdint>
#include <math.h>

#define B_ 2
#define E_ 32768
#define D_ 512
#define G_ 2048

// ---------------- scratch ------------------------------------------------------------
__device__ float  g_LV[(size_t)B_ * E_ * 1024];     // [m, 0:512]=logits, [m,512:1024]=vals
__device__ __half g_xhi[(size_t)B_ * E_ * D_];
__device__ __half g_xlo[(size_t)B_ * E_ * D_];
__device__ __half g_wstk[1024 * 512];               // [Wg; Wf] fp16
__device__ float  g_bstk[1024];
__device__ __half g_wh[D_ * D_];
__device__ __half g_yhi[(size_t)B_ * G_ * D_], g_ylo[(size_t)B_ * G_ * D_];
__device__ float  g_of[(size_t)B_ * G_ * D_];
__device__ int    g_cnt[G_], g_start[G_ + 1], g_cursor[G_], g_order[E_];

// ---------------- PTX helpers ---------------------------------------------------------
__device__ __forceinline__ uint32_t smem_u32(const void* p) {
    uint32_t a;
    asm("{ .reg .u64 t; cvta.to.shared.u64 t, %1; cvt.u32.u64 %0, t; }" : "=r"(a) : "l"(p));
    return a;
}
__device__ __forceinline__ void cp16(uint32_t s, const void* g) {
    asm volatile("cp.async.cg.shared.global [%0], [%1], 16;" :: "r"(s), "l"(g));
}
#define CP_COMMIT() asm volatile("cp.async.commit_group;" ::: "memory")
#define CP_WAIT(n)  asm volatile("cp.async.wait_group %0;" :: "n"(n) : "memory")

__device__ __forceinline__ void ldsm4(uint32_t* r, uint32_t addr) {
    asm volatile("ldmatrix.sync.aligned.m8n8.x4.shared.b16 {%0,%1,%2,%3}, [%4];"
                 : "=r"(r[0]), "=r"(r[1]), "=r"(r[2]), "=r"(r[3]) : "r"(addr));
}
__device__ __forceinline__ void mma_f16(float* c, const uint32_t* a, const uint32_t* b) {
    asm volatile(
        "mma.sync.aligned.m16n8k16.row.col.f32.f16.f16.f32 "
        "{%0,%1,%2,%3}, {%4,%5,%6,%7}, {%8,%9}, {%0,%1,%2,%3};"
        : "+f"(c[0]), "+f"(c[1]), "+f"(c[2]), "+f"(c[3])
        : "r"(a[0]), "r"(a[1]), "r"(a[2]), "r"(a[3]), "r"(b[0]), "r"(b[1]));
}

// ---------------- conversions -----------------------------------------------------------
__global__ void cvt_hilo4(const float* __restrict__ s, __half* __restrict__ hi,
                          __half* __restrict__ lo, size_t n4) {
    size_t i = (size_t)blockIdx.x * blockDim.x + threadIdx.x;
    if (i >= n4) return;
    float4 f = ((const float4*)s)[i];
    __half h0 = __float2half(f.x), h1 = __float2half(f.y);
    __half h2 = __float2half(f.z), h3 = __float2half(f.w);
    __half l0 = __float2half(f.x - __half2float(h0));
    __half l1 = __float2half(f.y - __half2float(h1));
    __half l2 = __float2half(f.z - __half2float(h2));
    __half l3 = __float2half(f.w - __half2float(h3));
    ((__half2*)hi)[2 * i]     = __halves2half2(h0, h1);
    ((__half2*)hi)[2 * i + 1] = __halves2half2(h2, h3);
    ((__half2*)lo)[2 * i]     = __halves2half2(l0, l1);
    ((__half2*)lo)[2 * i + 1] = __halves2half2(l2, l3);
}

__global__ void cvt_f16(const float* __restrict__ s, __half* __restrict__ d, size_t n4) {
    size_t i = (size_t)blockIdx.x * blockDim.x + threadIdx.x;
    if (i >= n4) return;
    float4 f = ((const float4*)s)[i];
    ((__half2*)d)[2 * i]     = __halves2half2(__float2half(f.x), __float2half(f.y));
    ((__half2*)d)[2 * i + 1] = __halves2half2(__float2half(f.z), __float2half(f.w));
}

__global__ void stack_bias(const float* __restrict__ bg, const float* __restrict__ bf) {
    int t = threadIdx.x + blockIdx.x * blockDim.x;
    if (t < 512) { g_bstk[t] = bg[t]; g_bstk[512 + t] = bf[t]; }
}

// ---------------- CSR build -------------------------------------------------------------
__global__ void zero_cnt() {
    int t = threadIdx.x + blockIdx.x * blockDim.x;
    if (t < G_) g_cnt[t] = 0;
}
__global__ void hist_k(const int* __restrict__ ix) {
    int e = threadIdx.x + blockIdx.x * blockDim.x;
    if (e < E_) atomicAdd(&g_cnt[ix[e]], 1);
}
__global__ void scan_k() {   // 1 block, 1024 threads, 2 elems each
    __shared__ int ps[1024];
    int t = threadIdx.x;
    int c0 = g_cnt[2 * t], c1 = g_cnt[2 * t + 1];
    ps[t] = c0 + c1;
    __syncthreads();
#pragma unroll
    for (int off = 1; off < 1024; off <<= 1) {
        int v = (t >= off) ? ps[t - off] : 0;
        __syncthreads();
        ps[t] += v;
        __syncthreads();
    }
    int excl = (t > 0) ? ps[t - 1] : 0;
    g_start[2 * t] = excl;          g_cursor[2 * t] = excl;
    g_start[2 * t + 1] = excl + c0; g_cursor[2 * t + 1] = excl + c0;
    if (t == 1023) g_start[2048] = ps[1023];
}
__global__ void scatter_k(const int* __restrict__ ix) {
    int e = threadIdx.x + blockIdx.x * blockDim.x;
    if (e >= E_) return;
    int idx = atomicAdd(&g_cursor[ix[e]], 1);
    g_order[idx] = e;
}

// ---------------- fp16x2 GEMM on mma.sync, 4-stage pipeline ------------------------------
// C[m][n] = sum_k A[m][k]*W[n][k] + bias[n]; A = Ah+Al (fp16 split), W = fp16.
// K=512, CTA tile 128x256, BK=32, 512 threads (4x4 warps, warp tile 32x64).
// MMA schedule: all-hi then all-lo per k16 slice -> same-acc reuse distance 16.
#define PITCH 80
#define ABUF  10240            // 128 rows * 80
#define BBUF  20480            // 256 rows * 80
#define BUFSZ 40960            // Ah + Al + B per stage
#define NSTAGE 4
#define SMEM_GEMM (NSTAGE * BUFSZ)  // 163840

__global__ __launch_bounds__(512, 1)
void gemm2t(const __half* __restrict__ Ahi, const __half* __restrict__ Alo,
            const __half* __restrict__ Bw,
            const float* __restrict__ bias, float* __restrict__ C, int ldc) {
    extern __shared__ char smem[];
    const uint32_t sb = smem_u32(smem);
    const int tid = threadIdx.x, lane = tid & 31, wid = tid >> 5;
    const int wm = wid >> 2, wn = wid & 3;
    const int m0 = blockIdx.y * 128, n0 = blockIdx.x * 256;

    float acc[2][8][4];
#pragma unroll
    for (int mt = 0; mt < 2; mt++)
#pragma unroll
        for (int nt = 0; nt < 8; nt++)
#pragma unroll
            for (int q = 0; q < 4; q++) acc[mt][nt][q] = 0.0f;

    // 2048 16B chunks per stage, 4 per thread
    auto load_buf = [&](int kc, int buf) {
        const int k0 = kc * 32;
        const uint32_t bb = sb + buf * BUFSZ;
#pragma unroll
        for (int t = 0; t < 4; t++) {
            int q = tid + t * 512;
            const __half* src;
            uint32_t base;
            int qq;
            if (q < 512)       { src = Ahi; base = 0;        qq = q; }
            else if (q < 1024) { src = Alo; base = ABUF;     qq = q - 512; }
            else               { src = Bw;  base = 2 * ABUF; qq = q - 1024; }
            int row = qq >> 2, c = qq & 3;
            int grow = (q < 1024) ? (m0 + row) : (n0 + row);
            cp16(bb + base + (uint32_t)(row * PITCH + c * 16),
                 src + (size_t)grow * 512 + k0 + c * 8);
        }
    };

    load_buf(0, 0); CP_COMMIT();
    load_buf(1, 1); CP_COMMIT();
    load_buf(2, 2); CP_COMMIT();

    const uint32_t a_lane = (uint32_t)((wm * 32 + (lane & 15)) * PITCH + (lane >> 4) * 16);
    const uint32_t b_lane = (uint32_t)((wn * 64 + ((lane >> 4) & 1) * 8 + (lane & 7)) * PITCH +
                                       ((lane >> 3) & 1) * 16);

    for (int kc = 0; kc < 16; kc++) {
        CP_WAIT(2);
        __syncthreads();
        if (kc + 3 < 16) load_buf(kc + 3, (kc + 3) & (NSTAGE - 1));
        CP_COMMIT();

        const uint32_t bb = sb + (kc & (NSTAGE - 1)) * BUFSZ;
#pragma unroll
        for (int ks = 0; ks < 2; ks++) {
            uint32_t ah[2][4], al[2][4], bfr[4][4];
            uint32_t aoff = a_lane + (uint32_t)(ks * 32);
            ldsm4(ah[0], bb + aoff);
            ldsm4(ah[1], bb + aoff + 16 * PITCH);
            ldsm4(al[0], bb + ABUF + aoff);
            ldsm4(al[1], bb + ABUF + aoff + 16 * PITCH);
#pragma unroll
            for (int np = 0; np < 4; np++)
                ldsm4(bfr[np], bb + 2 * ABUF + b_lane +
                                  (uint32_t)(np * 16 * PITCH + ks * 32));
            // hi pass: 16 MMAs, all distinct accumulators
#pragma unroll
            for (int np = 0; np < 4; np++) {
                mma_f16(acc[0][2 * np],     ah[0], bfr[np]);
                mma_f16(acc[0][2 * np + 1], ah[0], bfr[np] + 2);
                mma_f16(acc[1][2 * np],     ah[1], bfr[np]);
                mma_f16(acc[1][2 * np + 1], ah[1], bfr[np] + 2);
            }
            // lo pass: same accs, reuse distance = 16 MMAs
#pragma unroll
            for (int np = 0; np < 4; np++) {
                mma_f16(acc[0][2 * np],     al[0], bfr[np]);
                mma_f16(acc[0][2 * np + 1], al[0], bfr[np] + 2);
                mma_f16(acc[1][2 * np],     al[1], bfr[np]);
                mma_f16(acc[1][2 * np + 1], al[1], bfr[np] + 2);
            }
        }
    }

    // epilogue: bias + direct stores
#pragma unroll
    for (int mt = 0; mt < 2; mt++) {
        int r0 = m0 + wm * 32 + mt * 16 + (lane >> 2);
#pragma unroll
        for (int nt = 0; nt < 8; nt++) {
            int col = n0 + wn * 64 + nt * 8 + (lane & 3) * 2;
            float b0 = bias[col], b1 = bias[col + 1];
            float2 v0 = make_float2(acc[mt][nt][0] + b0, acc[mt][nt][1] + b1);
            float2 v1 = make_float2(acc[mt][nt][2] + b0, acc[mt][nt][3] + b1);
            *(float2*)&C[(size_t)r0 * ldc + col]       = v0;
            *(float2*)&C[(size_t)(r0 + 8) * ldc + col] = v1;
        }
    }
}

// ---------------- per-group softmax-weighted reduction -----------------------------------
__global__ __launch_bounds__(128)
void segreduce_k() {
    int g = blockIdx.x, b = blockIdx.y;
    int t = threadIdx.x;                 // t covers d = 4t..4t+3
    int s = g_start[g], e_end = g_start[g + 1];

    float4 den = make_float4(0.f, 0.f, 0.f, 0.f);
    float4 num = make_float4(0.f, 0.f, 0.f, 0.f);
    const float4* LV4 = (const float4*)g_LV;

    for (int j = s; j < e_end; j++) {
        int e = g_order[j];
        size_t row = (size_t)b * E_ + e;
        float4 L = LV4[row * 256 + t];
        float4 V = LV4[row * 256 + 128 + t];
        float e0 = __expf(L.x), e1 = __expf(L.y), e2 = __expf(L.z), e3 = __expf(L.w);
        den.x += e0; den.y += e1; den.z += e2; den.w += e3;
        num.x += e0 * V.x; num.y += e1 * V.y; num.z += e2 * V.z; num.w += e3 * V.w;
    }
    float y0 = (den.x > 0.f) ? num.x / den.x : 0.f;
    float y1 = (den.y > 0.f) ? num.y / den.y : 0.f;
    float y2 = (den.z > 0.f) ? num.z / den.z : 0.f;
    float y3 = (den.w > 0.f) ? num.w / den.w : 0.f;

    __half h0 = __float2half(y0), h1 = __float2half(y1);
    __half h2 = __float2half(y2), h3 = __float2half(y3);
    __half l0 = __float2half(y0 - __half2float(h0));
    __half l1 = __float2half(y1 - __half2float(h1));
    __half l2 = __float2half(y2 - __half2float(h2));
    __half l3 = __float2half(y3 - __half2float(h3));

    size_t o2 = ((size_t)b * G_ + g) * 256 + (size_t)t * 2;   // half2 index
    ((__half2*)g_yhi)[o2]     = __halves2half2(h0, h1);
    ((__half2*)g_yhi)[o2 + 1] = __halves2half2(h2, h3);
    ((__half2*)g_ylo)[o2]     = __halves2half2(l0, l1);
    ((__half2*)g_ylo)[o2 + 1] = __halves2half2(l2, l3);
}

// ---------------- gather out[b,e,:] = of[b, ix[e], :] -------------------------------------
__global__ void gather_k(const int* __restrict__ ix, float4* __restrict__ out) {
    size_t i = (size_t)blockIdx.x * blockDim.x + threadIdx.x;
    const size_t n4 = (size_t)B_ * E_ * (D_ / 4);
    if (i >= n4) return;
    int    d4 = (int)(i & 127);
    size_t be = i >> 7;
    int    e  = (int)(be & (E_ - 1));
    int    b  = (int)(be >> 15);
    const float4* of4 = (const float4*)g_of;
    out[i] = of4[((size_t)b * G_ + ix[e]) * 128 + d4];
}

// ---------------- launcher -----------------------------------------------------------------
extern "C" void kernel_launch(void* const* d_in, const int* in_sizes, int n_in,
                              void* d_out, int out_size) {
    const float* x  = (const float*)d_in[0];
    const int*   ix = (const int*)d_in[1];
    const float* Wf = (const float*)d_in[2];
    const float* bf = (const float*)d_in[3];
    const float* Wg = (const float*)d_in[4];
    const float* bg = (const float*)d_in[5];
    const float* Wh = (const float*)d_in[6];
    const float* bh = (const float*)d_in[7];
    float* out = (float*)d_out;

    float* pLV;  cudaGetSymbolAddress((void**)&pLV, g_LV);
    float* pOF;  cudaGetSymbolAddress((void**)&pOF, g_of);
    __half *xhi, *xlo, *wstk, *wh, *yhi, *ylo;
    cudaGetSymbolAddress((void**)&xhi, g_xhi);
    cudaGetSymbolAddress((void**)&xlo, g_xlo);
    cudaGetSymbolAddress((void**)&wstk, g_wstk);
    cudaGetSymbolAddress((void**)&wh, g_wh);
    cudaGetSymbolAddress((void**)&yhi, g_yhi);
    cudaGetSymbolAddress((void**)&ylo, g_ylo);
    float* pbstk; cudaGetSymbolAddress((void**)&pbstk, g_bstk);

    cudaFuncSetAttribute(gemm2t, cudaFuncAttributeMaxDynamicSharedMemorySize, SMEM_GEMM);

    const int T = 256;

    // 0) conversions: x -> fp16 hi/lo; weights -> fp16; bias stack
    {
        size_t n4 = (size_t)B_ * E_ * D_ / 4;
        cvt_hilo4<<<(unsigned)((n4 + T - 1) / T), T>>>(x, xhi, xlo, n4);
        size_t w4 = (size_t)D_ * D_ / 4;
        cvt_f16<<<(unsigned)((w4 + T - 1) / T), T>>>(Wg, wstk, w4);
        cvt_f16<<<(unsigned)((w4 + T - 1) / T), T>>>(Wf, wstk + 512 * 512, w4);
        cvt_f16<<<(unsigned)((w4 + T - 1) / T), T>>>(Wh, wh, w4);
        stack_bias<<<2, 256>>>(bg, bf);
    }

    // 1) CSR build from ix
    zero_cnt<<<G_ / T, T>>>();
    hist_k<<<E_ / T, T>>>(ix);
    scan_k<<<1, 1024>>>();
    scatter_k<<<E_ / T, T>>>(ix);

    // 2) projections (stacked): LV = X @ [Wg;Wf]^T + [bg;bf]
    {
        dim3 grid(4, (B_ * E_) / 128);
        gemm2t<<<grid, 512, SMEM_GEMM>>>(xhi, xlo, wstk, pbstk, pLV, 1024);
    }

    // 3) per-group softmax-weighted reduce -> y (fp16 hi/lo, fused normalize)
    {
        dim3 grid(G_, B_);
        segreduce_k<<<grid, 128>>>();
    }

    // 4) of = y @ Wh^T + bh
    {
        dim3 grid(2, (B_ * G_) / 128);
        gemm2t<<<grid, 512, SMEM_GEMM>>>(yhi, ylo, wh, bh, pOF, 512);
    }

    // 5) gather to edges
    {
        size_t n4 = (size_t)B_ * E_ * (D_ / 4);
        gather_k<<<(unsigned)((n4 + T - 1) / T), T>>>(ix, (float4*)out);
    }
}

// round 7
// speedup vs baseline: 1.4146x; 1.4146x over previous
#include <cuda_runtime.h>
#include <cuda_fp16.h>
#include <cstdint>
#include <math.h>

#define B_ 2
#define E_ 32768
#define D_ 512
#define G_ 2048

// ---------------- scratch ------------------------------------------------------------
__device__ float  g_LV[(size_t)B_ * E_ * 1024];     // [m, 0:512]=logits, [m,512:1024]=vals
__device__ __half g_x16[(size_t)B_ * E_ * D_];
__device__ __half g_wstk[1024 * 512];               // [Wg; Wf] fp16
__device__ float  g_bstk[1024];
__device__ __half g_wh[D_ * D_];
__device__ __half g_y16[(size_t)B_ * G_ * D_];
__device__ float  g_of[(size_t)B_ * G_ * D_];
__device__ int    g_cnt[G_], g_start[G_ + 1], g_cursor[G_], g_order[E_];

// ---------------- PTX helpers ---------------------------------------------------------
__device__ __forceinline__ uint32_t smem_u32(const void* p) {
    uint32_t a;
    asm("{ .reg .u64 t; cvta.to.shared.u64 t, %1; cvt.u32.u64 %0, t; }" : "=r"(a) : "l"(p));
    return a;
}
__device__ __forceinline__ void cp16(uint32_t s, const void* g) {
    asm volatile("cp.async.cg.shared.global [%0], [%1], 16;" :: "r"(s), "l"(g));
}
#define CP_COMMIT() asm volatile("cp.async.commit_group;" ::: "memory")
#define CP_WAIT(n)  asm volatile("cp.async.wait_group %0;" :: "n"(n) : "memory")

__device__ __forceinline__ void ldsm4(uint32_t* r, uint32_t addr) {
    asm volatile("ldmatrix.sync.aligned.m8n8.x4.shared.b16 {%0,%1,%2,%3}, [%4];"
                 : "=r"(r[0]), "=r"(r[1]), "=r"(r[2]), "=r"(r[3]) : "r"(addr));
}
__device__ __forceinline__ void mma_f16(float* c, const uint32_t* a, const uint32_t* b) {
    asm volatile(
        "mma.sync.aligned.m16n8k16.row.col.f32.f16.f16.f32 "
        "{%0,%1,%2,%3}, {%4,%5,%6,%7}, {%8,%9}, {%0,%1,%2,%3};"
        : "+f"(c[0]), "+f"(c[1]), "+f"(c[2]), "+f"(c[3])
        : "r"(a[0]), "r"(a[1]), "r"(a[2]), "r"(a[3]), "r"(b[0]), "r"(b[1]));
}

// ---------------- conversions -----------------------------------------------------------
__global__ void cvt_f16(const float* __restrict__ s, __half* __restrict__ d, size_t n4) {
    size_t i = (size_t)blockIdx.x * blockDim.x + threadIdx.x;
    if (i >= n4) return;
    float4 f = ((const float4*)s)[i];
    ((__half2*)d)[2 * i]     = __halves2half2(__float2half(f.x), __float2half(f.y));
    ((__half2*)d)[2 * i + 1] = __halves2half2(__float2half(f.z), __float2half(f.w));
}

__global__ void stack_bias(const float* __restrict__ bg, const float* __restrict__ bf) {
    int t = threadIdx.x + blockIdx.x * blockDim.x;
    if (t < 512) { g_bstk[t] = bg[t]; g_bstk[512 + t] = bf[t]; }
}

// ---------------- CSR build -------------------------------------------------------------
__global__ void zero_cnt() {
    int t = threadIdx.x + blockIdx.x * blockDim.x;
    if (t < G_) g_cnt[t] = 0;
}
__global__ void hist_k(const int* __restrict__ ix) {
    int e = threadIdx.x + blockIdx.x * blockDim.x;
    if (e < E_) atomicAdd(&g_cnt[ix[e]], 1);
}
__global__ void scan_k() {   // 1 block, 1024 threads, 2 elems each
    __shared__ int ps[1024];
    int t = threadIdx.x;
    int c0 = g_cnt[2 * t], c1 = g_cnt[2 * t + 1];
    ps[t] = c0 + c1;
    __syncthreads();
#pragma unroll
    for (int off = 1; off < 1024; off <<= 1) {
        int v = (t >= off) ? ps[t - off] : 0;
        __syncthreads();
        ps[t] += v;
        __syncthreads();
    }
    int excl = (t > 0) ? ps[t - 1] : 0;
    g_start[2 * t] = excl;          g_cursor[2 * t] = excl;
    g_start[2 * t + 1] = excl + c0; g_cursor[2 * t + 1] = excl + c0;
    if (t == 1023) g_start[2048] = ps[1023];
}
__global__ void scatter_k(const int* __restrict__ ix) {
    int e = threadIdx.x + blockIdx.x * blockDim.x;
    if (e >= E_) return;
    int idx = atomicAdd(&g_cursor[ix[e]], 1);
    g_order[idx] = e;
}

// ---------------- fp16 GEMM on mma.sync, 4-stage pipeline --------------------------------
// C[m][n] = sum_k A[m][k]*W[n][k] + bias[n]; A, W fp16, fp32 accum.
// K=512, CTA tile 128x256, BK=32, 512 threads (4x4 warps, warp tile 32x64).
#define PITCH 80
#define ABUF  10240            // 128 rows * 80
#define BBUF  20480            // 256 rows * 80
#define BUFSZ 30720            // A + B per stage
#define NSTAGE 4
#define SMEM_GEMM (NSTAGE * BUFSZ)  // 122880

__global__ __launch_bounds__(512, 1)
void gemm16(const __half* __restrict__ A, const __half* __restrict__ Bw,
            const float* __restrict__ bias, float* __restrict__ C, int ldc) {
    extern __shared__ char smem[];
    const uint32_t sb = smem_u32(smem);
    const int tid = threadIdx.x, lane = tid & 31, wid = tid >> 5;
    const int wm = wid >> 2, wn = wid & 3;
    const int m0 = blockIdx.y * 128, n0 = blockIdx.x * 256;

    float acc[2][8][4];
#pragma unroll
    for (int mt = 0; mt < 2; mt++)
#pragma unroll
        for (int nt = 0; nt < 8; nt++)
#pragma unroll
            for (int q = 0; q < 4; q++) acc[mt][nt][q] = 0.0f;

    // 1536 16B chunks per stage, 3 per thread
    auto load_buf = [&](int kc, int buf) {
        const int k0 = kc * 32;
        const uint32_t bb = sb + buf * BUFSZ;
#pragma unroll
        for (int t = 0; t < 3; t++) {
            int q = tid + t * 512;
            const __half* src;
            uint32_t base;
            int qq;
            if (q < 512) { src = A;  base = 0;    qq = q; }
            else         { src = Bw; base = ABUF; qq = q - 512; }
            int row = qq >> 2, c = qq & 3;
            int grow = (q < 512) ? (m0 + row) : (n0 + row);
            cp16(bb + base + (uint32_t)(row * PITCH + c * 16),
                 src + (size_t)grow * 512 + k0 + c * 8);
        }
    };

    load_buf(0, 0); CP_COMMIT();
    load_buf(1, 1); CP_COMMIT();
    load_buf(2, 2); CP_COMMIT();

    const uint32_t a_lane = (uint32_t)((wm * 32 + (lane & 15)) * PITCH + (lane >> 4) * 16);
    const uint32_t b_lane = (uint32_t)((wn * 64 + ((lane >> 4) & 1) * 8 + (lane & 7)) * PITCH +
                                       ((lane >> 3) & 1) * 16);

    for (int kc = 0; kc < 16; kc++) {
        CP_WAIT(2);
        __syncthreads();
        if (kc + 3 < 16) load_buf(kc + 3, (kc + 3) & (NSTAGE - 1));
        CP_COMMIT();

        const uint32_t bb = sb + (kc & (NSTAGE - 1)) * BUFSZ;
#pragma unroll
        for (int ks = 0; ks < 2; ks++) {
            uint32_t ah[2][4], bfr[4][4];
            uint32_t aoff = a_lane + (uint32_t)(ks * 32);
            ldsm4(ah[0], bb + aoff);
            ldsm4(ah[1], bb + aoff + 16 * PITCH);
#pragma unroll
            for (int np = 0; np < 4; np++)
                ldsm4(bfr[np], bb + ABUF + b_lane +
                                  (uint32_t)(np * 16 * PITCH + ks * 32));
#pragma unroll
            for (int np = 0; np < 4; np++) {
                mma_f16(acc[0][2 * np],     ah[0], bfr[np]);
                mma_f16(acc[0][2 * np + 1], ah[0], bfr[np] + 2);
                mma_f16(acc[1][2 * np],     ah[1], bfr[np]);
                mma_f16(acc[1][2 * np + 1], ah[1], bfr[np] + 2);
            }
        }
    }

    // epilogue: bias + direct stores
#pragma unroll
    for (int mt = 0; mt < 2; mt++) {
        int r0 = m0 + wm * 32 + mt * 16 + (lane >> 2);
#pragma unroll
        for (int nt = 0; nt < 8; nt++) {
            int col = n0 + wn * 64 + nt * 8 + (lane & 3) * 2;
            float b0 = bias[col], b1 = bias[col + 1];
            float2 v0 = make_float2(acc[mt][nt][0] + b0, acc[mt][nt][1] + b1);
            float2 v1 = make_float2(acc[mt][nt][2] + b0, acc[mt][nt][3] + b1);
            *(float2*)&C[(size_t)r0 * ldc + col]       = v0;
            *(float2*)&C[(size_t)(r0 + 8) * ldc + col] = v1;
        }
    }
}

// ---------------- per-group softmax-weighted reduction -----------------------------------
__global__ __launch_bounds__(128)
void segreduce_k() {
    int g = blockIdx.x, b = blockIdx.y;
    int t = threadIdx.x;                 // t covers d = 4t..4t+3
    int s = g_start[g], e_end = g_start[g + 1];

    float4 den = make_float4(0.f, 0.f, 0.f, 0.f);
    float4 num = make_float4(0.f, 0.f, 0.f, 0.f);
    const float4* LV4 = (const float4*)g_LV;

    for (int j = s; j < e_end; j++) {
        int e = g_order[j];
        size_t row = (size_t)b * E_ + e;
        float4 L = LV4[row * 256 + t];
        float4 V = LV4[row * 256 + 128 + t];
        float e0 = __expf(L.x), e1 = __expf(L.y), e2 = __expf(L.z), e3 = __expf(L.w);
        den.x += e0; den.y += e1; den.z += e2; den.w += e3;
        num.x += e0 * V.x; num.y += e1 * V.y; num.z += e2 * V.z; num.w += e3 * V.w;
    }
    float y0 = (den.x > 0.f) ? num.x / den.x : 0.f;
    float y1 = (den.y > 0.f) ? num.y / den.y : 0.f;
    float y2 = (den.z > 0.f) ? num.z / den.z : 0.f;
    float y3 = (den.w > 0.f) ? num.w / den.w : 0.f;

    size_t o2 = ((size_t)b * G_ + g) * 256 + (size_t)t * 2;   // half2 index
    ((__half2*)g_y16)[o2]     = __halves2half2(__float2half(y0), __float2half(y1));
    ((__half2*)g_y16)[o2 + 1] = __halves2half2(__float2half(y2), __float2half(y3));
}

// ---------------- gather out[b,e,:] = of[b, ix[e], :] -------------------------------------
__global__ void gather_k(const int* __restrict__ ix, float4* __restrict__ out) {
    size_t i = (size_t)blockIdx.x * blockDim.x + threadIdx.x;
    const size_t n4 = (size_t)B_ * E_ * (D_ / 4);
    if (i >= n4) return;
    int    d4 = (int)(i & 127);
    size_t be = i >> 7;
    int    e  = (int)(be & (E_ - 1));
    int    b  = (int)(be >> 15);
    const float4* of4 = (const float4*)g_of;
    out[i] = of4[((size_t)b * G_ + ix[e]) * 128 + d4];
}

// ---------------- launcher -----------------------------------------------------------------
extern "C" void kernel_launch(void* const* d_in, const int* in_sizes, int n_in,
                              void* d_out, int out_size) {
    const float* x  = (const float*)d_in[0];
    const int*   ix = (const int*)d_in[1];
    const float* Wf = (const float*)d_in[2];
    const float* bf = (const float*)d_in[3];
    const float* Wg = (const float*)d_in[4];
    const float* bg = (const float*)d_in[5];
    const float* Wh = (const float*)d_in[6];
    const float* bh = (const float*)d_in[7];
    float* out = (float*)d_out;

    float* pLV;  cudaGetSymbolAddress((void**)&pLV, g_LV);
    float* pOF;  cudaGetSymbolAddress((void**)&pOF, g_of);
    __half *x16, *wstk, *wh, *y16;
    cudaGetSymbolAddress((void**)&x16, g_x16);
    cudaGetSymbolAddress((void**)&wstk, g_wstk);
    cudaGetSymbolAddress((void**)&wh, g_wh);
    cudaGetSymbolAddress((void**)&y16, g_y16);
    float* pbstk; cudaGetSymbolAddress((void**)&pbstk, g_bstk);

    cudaFuncSetAttribute(gemm16, cudaFuncAttributeMaxDynamicSharedMemorySize, SMEM_GEMM);

    const int T = 256;

    // 0) conversions: x -> fp16; weights -> fp16; bias stack
    {
        size_t n4 = (size_t)B_ * E_ * D_ / 4;
        cvt_f16<<<(unsigned)((n4 + T - 1) / T), T>>>(x, x16, n4);
        size_t w4 = (size_t)D_ * D_ / 4;
        cvt_f16<<<(unsigned)((w4 + T - 1) / T), T>>>(Wg, wstk, w4);
        cvt_f16<<<(unsigned)((w4 + T - 1) / T), T>>>(Wf, wstk + 512 * 512, w4);
        cvt_f16<<<(unsigned)((w4 + T - 1) / T), T>>>(Wh, wh, w4);
        stack_bias<<<2, 256>>>(bg, bf);
    }

    // 1) CSR build from ix
    zero_cnt<<<G_ / T, T>>>();
    hist_k<<<E_ / T, T>>>(ix);
    scan_k<<<1, 1024>>>();
    scatter_k<<<E_ / T, T>>>(ix);

    // 2) projections (stacked): LV = X @ [Wg;Wf]^T + [bg;bf]
    {
        dim3 grid(4, (B_ * E_) / 128);
        gemm16<<<grid, 512, SMEM_GEMM>>>(x16, wstk, pbstk, pLV, 1024);
    }

    // 3) per-group softmax-weighted reduce -> y (fp16, fused normalize)
    {
        dim3 grid(G_, B_);
        segreduce_k<<<grid, 128>>>();
    }

    // 4) of = y @ Wh^T + bh
    {
        dim3 grid(2, (B_ * G_) / 128);
        gemm16<<<grid, 512, SMEM_GEMM>>>(y16, wh, bh, pOF, 512);
    }

    // 5) gather to edges
    {
        size_t n4 = (size_t)B_ * E_ * (D_ / 4);
        gather_k<<<(unsigned)((n4 + T - 1) / T), T>>>(ix, (float4*)out);
    }
}

// round 8
// speedup vs baseline: 1.4574x; 1.0302x over previous
#include <cuda_runtime.h>
#include <cuda_fp16.h>
#include <cstdint>
#include <math.h>

#define B_ 2
#define E_ 32768
#define D_ 512
#define G_ 2048

// ---------------- scratch ------------------------------------------------------------
// EV: [m, 0:512] = exp(logit) fp16, [m, 512:1024] = val fp16
__device__ __half g_EV[(size_t)B_ * E_ * 1024];
__device__ __half g_x16[(size_t)B_ * E_ * D_];
__device__ __half g_wstk[1024 * 512];               // [Wg; Wf] fp16
__device__ float  g_bstk[1024];
__device__ __half g_wh[D_ * D_];
__device__ __half g_y16[(size_t)B_ * G_ * D_];
__device__ float  g_of[(size_t)B_ * G_ * D_];
__device__ int    g_cnt[G_], g_start[G_ + 1], g_cursor[G_], g_order[E_];

// ---------------- PTX helpers ---------------------------------------------------------
__device__ __forceinline__ uint32_t smem_u32(const void* p) {
    uint32_t a;
    asm("{ .reg .u64 t; cvta.to.shared.u64 t, %1; cvt.u32.u64 %0, t; }" : "=r"(a) : "l"(p));
    return a;
}
__device__ __forceinline__ void cp16(uint32_t s, const void* g) {
    asm volatile("cp.async.cg.shared.global [%0], [%1], 16;" :: "r"(s), "l"(g));
}
#define CP_COMMIT() asm volatile("cp.async.commit_group;" ::: "memory")
#define CP_WAIT(n)  asm volatile("cp.async.wait_group %0;" :: "n"(n) : "memory")

__device__ __forceinline__ void ldsm4(uint32_t* r, uint32_t addr) {
    asm volatile("ldmatrix.sync.aligned.m8n8.x4.shared.b16 {%0,%1,%2,%3}, [%4];"
                 : "=r"(r[0]), "=r"(r[1]), "=r"(r[2]), "=r"(r[3]) : "r"(addr));
}
__device__ __forceinline__ void mma_f16(float* c, const uint32_t* a, const uint32_t* b) {
    asm volatile(
        "mma.sync.aligned.m16n8k16.row.col.f32.f16.f16.f32 "
        "{%0,%1,%2,%3}, {%4,%5,%6,%7}, {%8,%9}, {%0,%1,%2,%3};"
        : "+f"(c[0]), "+f"(c[1]), "+f"(c[2]), "+f"(c[3])
        : "r"(a[0]), "r"(a[1]), "r"(a[2]), "r"(a[3]), "r"(b[0]), "r"(b[1]));
}

// ---------------- conversions -----------------------------------------------------------
__global__ void cvt_f16(const float* __restrict__ s, __half* __restrict__ d, size_t n4) {
    size_t i = (size_t)blockIdx.x * blockDim.x + threadIdx.x;
    if (i >= n4) return;
    float4 f = ((const float4*)s)[i];
    ((__half2*)d)[2 * i]     = __halves2half2(__float2half(f.x), __float2half(f.y));
    ((__half2*)d)[2 * i + 1] = __halves2half2(__float2half(f.z), __float2half(f.w));
}

// one kernel: Wg,Wf -> g_wstk, Wh -> g_wh, bg/bf -> g_bstk
__global__ void cvt_wb(const float* __restrict__ Wg, const float* __restrict__ Wf,
                       const float* __restrict__ Wh,
                       const float* __restrict__ bg, const float* __restrict__ bf) {
    int bid = blockIdx.x, t = threadIdx.x;
    if (bid < 768) {
        const float* src = (bid < 256) ? Wg : ((bid < 512) ? Wf : Wh);
        __half* dst = (bid < 256) ? g_wstk : ((bid < 512) ? (g_wstk + 512 * 512) : g_wh);
        int i = (bid & 255) * 256 + t;                    // float4 index, 65536 per matrix
        float4 f = ((const float4*)src)[i];
        ((__half2*)dst)[2 * i]     = __halves2half2(__float2half(f.x), __float2half(f.y));
        ((__half2*)dst)[2 * i + 1] = __halves2half2(__float2half(f.z), __float2half(f.w));
    } else {
        for (int q = t; q < 1024; q += 256)
            g_bstk[q] = (q < 512) ? bg[q] : bf[q - 512];
    }
}

// ---------------- CSR build -------------------------------------------------------------
__global__ void hist_k(const int* __restrict__ ix) {
    int e = threadIdx.x + blockIdx.x * blockDim.x;
    if (e < E_) atomicAdd(&g_cnt[ix[e]], 1);
}
__global__ void scan_k() {   // 1 block, 1024 threads, 2 elems each; self-zeros g_cnt
    __shared__ int ps[1024];
    int t = threadIdx.x;
    int c0 = g_cnt[2 * t], c1 = g_cnt[2 * t + 1];
    g_cnt[2 * t] = 0; g_cnt[2 * t + 1] = 0;          // reset for next graph replay
    ps[t] = c0 + c1;
    __syncthreads();
#pragma unroll
    for (int off = 1; off < 1024; off <<= 1) {
        int v = (t >= off) ? ps[t - off] : 0;
        __syncthreads();
        ps[t] += v;
        __syncthreads();
    }
    int excl = (t > 0) ? ps[t - 1] : 0;
    g_start[2 * t] = excl;          g_cursor[2 * t] = excl;
    g_start[2 * t + 1] = excl + c0; g_cursor[2 * t + 1] = excl + c0;
    if (t == 1023) g_start[2048] = ps[1023];
}
__global__ void scatter_k(const int* __restrict__ ix) {
    int e = threadIdx.x + blockIdx.x * blockDim.x;
    if (e >= E_) return;
    int idx = atomicAdd(&g_cursor[ix[e]], 1);
    g_order[idx] = e;
}

// ---------------- fp16 GEMM on mma.sync, 4-stage pipeline --------------------------------
// MODE 0: C fp32 = A@W^T + bias (ldc cols)
// MODE 1: C fp16; cols < 512 get exp() applied (logits half), rest plain (vals half)
#define PITCH 80
#define ABUF  10240            // 128 rows * 80
#define BBUF  20480            // 256 rows * 80
#define BUFSZ 30720            // A + B per stage
#define NSTAGE 4
#define SMEM_GEMM (NSTAGE * BUFSZ)  // 122880

template<int MODE>
__global__ __launch_bounds__(512, 1)
void gemm16(const __half* __restrict__ A, const __half* __restrict__ Bw,
            const float* __restrict__ bias, void* __restrict__ Cout, int ldc) {
    extern __shared__ char smem[];
    const uint32_t sb = smem_u32(smem);
    const int tid = threadIdx.x, lane = tid & 31, wid = tid >> 5;
    const int wm = wid >> 2, wn = wid & 3;
    const int m0 = blockIdx.y * 128, n0 = blockIdx.x * 256;

    float acc[2][8][4];
#pragma unroll
    for (int mt = 0; mt < 2; mt++)
#pragma unroll
        for (int nt = 0; nt < 8; nt++)
#pragma unroll
            for (int q = 0; q < 4; q++) acc[mt][nt][q] = 0.0f;

    auto load_buf = [&](int kc, int buf) {
        const int k0 = kc * 32;
        const uint32_t bb = sb + buf * BUFSZ;
#pragma unroll
        for (int t = 0; t < 3; t++) {
            int q = tid + t * 512;
            const __half* src;
            uint32_t base;
            int qq;
            if (q < 512) { src = A;  base = 0;    qq = q; }
            else         { src = Bw; base = ABUF; qq = q - 512; }
            int row = qq >> 2, c = qq & 3;
            int grow = (q < 512) ? (m0 + row) : (n0 + row);
            cp16(bb + base + (uint32_t)(row * PITCH + c * 16),
                 src + (size_t)grow * 512 + k0 + c * 8);
        }
    };

    load_buf(0, 0); CP_COMMIT();
    load_buf(1, 1); CP_COMMIT();
    load_buf(2, 2); CP_COMMIT();

    const uint32_t a_lane = (uint32_t)((wm * 32 + (lane & 15)) * PITCH + (lane >> 4) * 16);
    const uint32_t b_lane = (uint32_t)((wn * 64 + ((lane >> 4) & 1) * 8 + (lane & 7)) * PITCH +
                                       ((lane >> 3) & 1) * 16);

    for (int kc = 0; kc < 16; kc++) {
        CP_WAIT(2);
        __syncthreads();
        if (kc + 3 < 16) load_buf(kc + 3, (kc + 3) & (NSTAGE - 1));
        CP_COMMIT();

        const uint32_t bb = sb + (kc & (NSTAGE - 1)) * BUFSZ;
#pragma unroll
        for (int ks = 0; ks < 2; ks++) {
            uint32_t ah[2][4], bfr[4][4];
            uint32_t aoff = a_lane + (uint32_t)(ks * 32);
            ldsm4(ah[0], bb + aoff);
            ldsm4(ah[1], bb + aoff + 16 * PITCH);
#pragma unroll
            for (int np = 0; np < 4; np++)
                ldsm4(bfr[np], bb + ABUF + b_lane +
                                  (uint32_t)(np * 16 * PITCH + ks * 32));
#pragma unroll
            for (int np = 0; np < 4; np++) {
                mma_f16(acc[0][2 * np],     ah[0], bfr[np]);
                mma_f16(acc[0][2 * np + 1], ah[0], bfr[np] + 2);
                mma_f16(acc[1][2 * np],     ah[1], bfr[np]);
                mma_f16(acc[1][2 * np + 1], ah[1], bfr[np] + 2);
            }
        }
    }

    // epilogue
    const bool doexp = (MODE == 1) && (n0 < 512);
#pragma unroll
    for (int mt = 0; mt < 2; mt++) {
        int r0 = m0 + wm * 32 + mt * 16 + (lane >> 2);
#pragma unroll
        for (int nt = 0; nt < 8; nt++) {
            int col = n0 + wn * 64 + nt * 8 + (lane & 3) * 2;
            float b0 = bias[col], b1 = bias[col + 1];
            float v0 = acc[mt][nt][0] + b0, v1 = acc[mt][nt][1] + b1;
            float v2 = acc[mt][nt][2] + b0, v3 = acc[mt][nt][3] + b1;
            if (MODE == 0) {
                float* C = (float*)Cout;
                *(float2*)&C[(size_t)r0 * ldc + col]       = make_float2(v0, v1);
                *(float2*)&C[(size_t)(r0 + 8) * ldc + col] = make_float2(v2, v3);
            } else {
                if (doexp) { v0 = __expf(v0); v1 = __expf(v1); v2 = __expf(v2); v3 = __expf(v3); }
                __half* C = (__half*)Cout;
                *(__half2*)&C[(size_t)r0 * ldc + col]       = __floats2half2_rn(v0, v1);
                *(__half2*)&C[(size_t)(r0 + 8) * ldc + col] = __floats2half2_rn(v2, v3);
            }
        }
    }
}

// ---------------- per-group softmax-weighted reduction (fp16 EV input) --------------------
__global__ __launch_bounds__(128)
void segreduce_k() {
    int g = blockIdx.x, b = blockIdx.y;
    int t = threadIdx.x;                 // t covers d = 4t..4t+3
    int s = g_start[g], e_end = g_start[g + 1];

    float4 den = make_float4(0.f, 0.f, 0.f, 0.f);
    float4 num = make_float4(0.f, 0.f, 0.f, 0.f);

    for (int j = s; j < e_end; j++) {
        int e = g_order[j];
        const __half2* row = (const __half2*)(g_EV + ((size_t)b * E_ + e) * 1024);
        __half2 w01 = row[2 * t],       w23 = row[2 * t + 1];
        __half2 v01 = row[256 + 2 * t], v23 = row[256 + 2 * t + 1];
        float2 w0 = __half22float2(w01), w1 = __half22float2(w23);
        float2 x0 = __half22float2(v01), x1 = __half22float2(v23);
        den.x += w0.x; den.y += w0.y; den.z += w1.x; den.w += w1.y;
        num.x += w0.x * x0.x; num.y += w0.y * x0.y;
        num.z += w1.x * x1.x; num.w += w1.y * x1.y;
    }
    float y0 = (den.x > 0.f) ? num.x / den.x : 0.f;
    float y1 = (den.y > 0.f) ? num.y / den.y : 0.f;
    float y2 = (den.z > 0.f) ? num.z / den.z : 0.f;
    float y3 = (den.w > 0.f) ? num.w / den.w : 0.f;

    size_t o2 = ((size_t)b * G_ + g) * 256 + (size_t)t * 2;   // half2 index
    ((__half2*)g_y16)[o2]     = __floats2half2_rn(y0, y1);
    ((__half2*)g_y16)[o2 + 1] = __floats2half2_rn(y2, y3);
}

// ---------------- gather out[b,e,:] = of[b, ix[e], :] -------------------------------------
__global__ void gather_k(const int* __restrict__ ix, float4* __restrict__ out) {
    size_t i = (size_t)blockIdx.x * blockDim.x + threadIdx.x;
    const size_t n4 = (size_t)B_ * E_ * (D_ / 4);
    if (i >= n4) return;
    int    d4 = (int)(i & 127);
    size_t be = i >> 7;
    int    e  = (int)(be & (E_ - 1));
    int    b  = (int)(be >> 15);
    const float4* of4 = (const float4*)g_of;
    out[i] = of4[((size_t)b * G_ + ix[e]) * 128 + d4];
}

// ---------------- launcher -----------------------------------------------------------------
extern "C" void kernel_launch(void* const* d_in, const int* in_sizes, int n_in,
                              void* d_out, int out_size) {
    const float* x  = (const float*)d_in[0];
    const int*   ix = (const int*)d_in[1];
    const float* Wf = (const float*)d_in[2];
    const float* bf = (const float*)d_in[3];
    const float* Wg = (const float*)d_in[4];
    const float* bg = (const float*)d_in[5];
    const float* Wh = (const float*)d_in[6];
    const float* bh = (const float*)d_in[7];
    float* out = (float*)d_out;

    __half *x16, *wstk, *wh, *y16, *ev;
    cudaGetSymbolAddress((void**)&x16, g_x16);
    cudaGetSymbolAddress((void**)&wstk, g_wstk);
    cudaGetSymbolAddress((void**)&wh, g_wh);
    cudaGetSymbolAddress((void**)&y16, g_y16);
    cudaGetSymbolAddress((void**)&ev, g_EV);
    float *pbstk, *pOF;
    cudaGetSymbolAddress((void**)&pbstk, g_bstk);
    cudaGetSymbolAddress((void**)&pOF, g_of);

    cudaFuncSetAttribute(gemm16<0>, cudaFuncAttributeMaxDynamicSharedMemorySize, SMEM_GEMM);
    cudaFuncSetAttribute(gemm16<1>, cudaFuncAttributeMaxDynamicSharedMemorySize, SMEM_GEMM);

    const int T = 256;

    // launch 0: x -> fp16
    {
        size_t n4 = (size_t)B_ * E_ * D_ / 4;
        cvt_f16<<<(unsigned)((n4 + T - 1) / T), T>>>(x, x16, n4);
    }
    // launch 1: all weights + bias
    cvt_wb<<<769, 256>>>(Wg, Wf, Wh, bg, bf);
    // launches 2-4: CSR build
    hist_k<<<E_ / T, T>>>(ix);
    scan_k<<<1, 1024>>>();
    scatter_k<<<E_ / T, T>>>(ix);
    // launch 5: projections (stacked) -> EV fp16 (exp applied to logit half)
    {
        dim3 grid(4, (B_ * E_) / 128);
        gemm16<1><<<grid, 512, SMEM_GEMM>>>(x16, wstk, pbstk, ev, 1024);
    }
    // launch 6: per-group softmax-weighted reduce -> y16
    {
        dim3 grid(G_, B_);
        segreduce_k<<<grid, 128>>>();
    }
    // launch 7: of = y @ Wh^T + bh (fp32 out)
    {
        dim3 grid(2, (B_ * G_) / 128);
        gemm16<0><<<grid, 512, SMEM_GEMM>>>(y16, wh, bh, pOF, 512);
    }
    // launch 8: gather to edges
    {
        size_t n4 = (size_t)B_ * E_ * (D_ / 4);
        gather_k<<<(unsigned)((n4 + T - 1) / T), T>>>(ix, (float4*)out);
    }
}